// round 1
// baseline (speedup 1.0000x reference)
#include <cuda_runtime.h>

#define B 4096
#define D 128
#define TILE 128
#define NCH (B / TILE)   // 32 j-chunks
#define NTHREADS 256

// ---- scratch (no allocations allowed) ----
__device__ unsigned long long g_bits[B];
__device__ float g_cnt[B];
__device__ float g_M[B * NCH];
__device__ float g_S[B * NCH];
__device__ float g_A[B * NCH];   // sum mask*x (unshifted)
__device__ float g_W[B * NCH];   // sum mask
__device__ float g_P[B * NCH];   // count positives
__device__ float g_bsum[32];

// Pack multi-hot labels into 64-bit masks + counts.
__global__ void pack_labels(const float* __restrict__ L) {
    int row = blockIdx.x * 256 + threadIdx.x;
    if (row < B) {
        unsigned long long b = 0ull;
        float c = 0.f;
#pragma unroll
        for (int k = 0; k < 50; k++) {
            if (L[row * 50 + k] > 0.5f) { b |= (1ull << k); c += 1.f; }
        }
        g_bits[row] = b;
        g_cnt[row] = c;
    }
}

// One CTA per (i-tile, j-tile): 128x128 dot tile + fused per-row partial stats.
__global__ __launch_bounds__(NTHREADS, 1) void supcon_tile(const float* __restrict__ F) {
    extern __shared__ char smem_raw[];
    float* FiT = (float*)smem_raw;                 // [k][i] transposed, 128x128
    float* FjT = FiT + TILE * D;                   // [k][j]
    unsigned long long* bitsI = (unsigned long long*)(FjT + TILE * D);
    unsigned long long* bitsJ = bitsI + TILE;
    float* cntI = (float*)(bitsJ + TILE);
    float* cntJ = cntI + TILE;

    const int jt = blockIdx.x, it = blockIdx.y;
    const int i0 = it * TILE, j0 = jt * TILE;
    const int tid = threadIdx.x;

    // Load feature tiles, transposing into [k][row] layout (conflict-free STS).
    for (int idx = tid; idx < TILE * (D / 4); idx += NTHREADS) {
        int r = idx & (TILE - 1);
        int k4 = idx >> 7;
        float4 v = *(const float4*)(F + (size_t)(i0 + r) * D + k4 * 4);
        FiT[(k4 * 4 + 0) * TILE + r] = v.x;
        FiT[(k4 * 4 + 1) * TILE + r] = v.y;
        FiT[(k4 * 4 + 2) * TILE + r] = v.z;
        FiT[(k4 * 4 + 3) * TILE + r] = v.w;
        float4 u = *(const float4*)(F + (size_t)(j0 + r) * D + k4 * 4);
        FjT[(k4 * 4 + 0) * TILE + r] = u.x;
        FjT[(k4 * 4 + 1) * TILE + r] = u.y;
        FjT[(k4 * 4 + 2) * TILE + r] = u.z;
        FjT[(k4 * 4 + 3) * TILE + r] = u.w;
    }
    if (tid < TILE) {
        bitsI[tid] = g_bits[i0 + tid];
        cntI[tid]  = g_cnt[i0 + tid];
        bitsJ[tid] = g_bits[j0 + tid];
        cntJ[tid]  = g_cnt[j0 + tid];
    }
    __syncthreads();

    const int ty = tid >> 4;   // 0..15 -> i micro-row group
    const int tx = tid & 15;   // 0..15 -> j micro-col group

    float acc[8][8];
#pragma unroll
    for (int r = 0; r < 8; r++)
#pragma unroll
        for (int c = 0; c < 8; c++) acc[r][c] = 0.f;

    const float* ap = FiT + ty * 8;
    const float* bp = FjT + tx * 8;
#pragma unroll 2
    for (int k = 0; k < D; k++) {
        float4 a0 = *(const float4*)(ap + k * TILE);
        float4 a1 = *(const float4*)(ap + k * TILE + 4);
        float4 b0 = *(const float4*)(bp + k * TILE);
        float4 b1 = *(const float4*)(bp + k * TILE + 4);
        float a[8] = {a0.x, a0.y, a0.z, a0.w, a1.x, a1.y, a1.z, a1.w};
        float b[8] = {b0.x, b0.y, b0.z, b0.w, b1.x, b1.y, b1.z, b1.w};
#pragma unroll
        for (int r = 0; r < 8; r++)
#pragma unroll
            for (int c = 0; c < 8; c++)
                acc[r][c] = fmaf(a[r], b[c], acc[r][c]);
    }

    // Epilogue: per i-row stats over this 128-wide j-chunk.
    const float invT = 1.0f / 0.07f;
#pragma unroll 1
    for (int r = 0; r < 8; r++) {
        const int il = ty * 8 + r;
        const int gi = i0 + il;
        const unsigned long long bi = bitsI[il];
        const float ci = cntI[il];

        float xs[8];
        float lmax = -3.4e38f;
#pragma unroll
        for (int c = 0; c < 8; c++) {
            xs[c] = acc[r][c] * invT;
            lmax = fmaxf(lmax, xs[c]);
        }
        // max over the 16 lanes sharing this i-row (offsets <16 stay in-group)
#pragma unroll
        for (int o = 1; o < 16; o <<= 1)
            lmax = fmaxf(lmax, __shfl_xor_sync(0xffffffffu, lmax, o));

        float lS = 0.f, lA = 0.f, lW = 0.f, lP = 0.f;
#pragma unroll
        for (int c = 0; c < 8; c++) {
            const int jl = tx * 8 + c;
            const int gj = j0 + jl;
            if (gi != gj) {
                lS += __expf(xs[c] - lmax);
                const float cj = cntJ[jl];
                const float tm = fmaxf(ci, cj);
                const float inter = (float)__popcll(bi & bitsJ[jl]);
                const float mu = (tm > 0.f) ? __fdividef(inter, tm) : 0.f;
                lA = fmaf(mu, xs[c], lA);
                lW += mu;
                lP += (inter > 0.f) ? 1.f : 0.f;
            }
        }
#pragma unroll
        for (int o = 1; o < 16; o <<= 1) {
            lS += __shfl_xor_sync(0xffffffffu, lS, o);
            lA += __shfl_xor_sync(0xffffffffu, lA, o);
            lW += __shfl_xor_sync(0xffffffffu, lW, o);
            lP += __shfl_xor_sync(0xffffffffu, lP, o);
        }
        if (tx == 0) {
            const int o = gi * NCH + jt;
            g_M[o] = lmax;
            g_S[o] = lS;
            g_A[o] = lA;
            g_W[o] = lW;
            g_P[o] = lP;
        }
    }
}

// Merge the 32 j-chunk partials per row (exact LSE merge), reduce per block.
__global__ void row_reduce() {
    const int tid = threadIdx.x;
    const int row = blockIdx.x * 128 + tid;

    float m = -3.4e38f;
#pragma unroll
    for (int c = 0; c < NCH; c++) m = fmaxf(m, g_M[row * NCH + c]);
    float S = 0.f, A = 0.f, W = 0.f, P = 0.f;
#pragma unroll
    for (int c = 0; c < NCH; c++) {
        const int o = row * NCH + c;
        S += g_S[o] * __expf(g_M[o] - m);
        A += g_A[o];
        W += g_W[o];
        P += g_P[o];
    }
    A -= m * W;                                    // sum mask*(x - m)
    float v = (A - W * logf(S + 1e-12f)) / (P + 1e-12f);

    __shared__ float red[128];
    red[tid] = v;
    __syncthreads();
#pragma unroll
    for (int s = 64; s > 0; s >>= 1) {
        if (tid < s) red[tid] += red[tid + s];
        __syncthreads();
    }
    if (tid == 0) g_bsum[blockIdx.x] = red[0];
}

__global__ void final_reduce(float* __restrict__ out) {
    float v = g_bsum[threadIdx.x];   // 32 threads, 32 partials
#pragma unroll
    for (int o = 16; o > 0; o >>= 1)
        v += __shfl_xor_sync(0xffffffffu, v, o);
    if (threadIdx.x == 0)
        out[0] = -(v * (1.0f / (float)B)) * 0.5f;   // -mean / 2^alpha
}

extern "C" void kernel_launch(void* const* d_in, const int* in_sizes, int n_in,
                              void* d_out, int out_size) {
    const float* F = (const float*)d_in[0];
    const float* L = (const float*)d_in[1];
    if (n_in >= 2 && in_sizes[0] == B * 50 && in_sizes[1] == B * D) {
        const float* t = F; F = L; L = t;   // defensive against input ordering
    }
    const int smem_bytes = TILE * D * 4 * 2        // FiT + FjT
                         + TILE * 8 * 2            // bitsI + bitsJ
                         + TILE * 4 * 2;           // cntI + cntJ
    cudaFuncSetAttribute(supcon_tile, cudaFuncAttributeMaxDynamicSharedMemorySize, smem_bytes);

    pack_labels<<<(B + 255) / 256, 256>>>(L);
    supcon_tile<<<dim3(NCH, NCH), NTHREADS, smem_bytes>>>(F);
    row_reduce<<<B / 128, 128>>>();
    final_reduce<<<1, 32>>>((float*)d_out);
}

// round 4
// speedup vs baseline: 2.7071x; 2.7071x over previous
#include <cuda_runtime.h>
#include <cuda_bf16.h>
#include <cstdint>

#define BATCH 4096
#define D 128
#define TM 128
#define TN 128
#define NTHR 256
#define NCH 64          // 4096 / 64-col warp chunk

// ---- device scratch (no allocations allowed) ----
__device__ __nv_bfloat16 g_fbf[BATCH * D];
__device__ unsigned long long g_bits[BATCH];
__device__ float g_cnt[BATCH];
__device__ float g_M[BATCH * NCH];
__device__ float g_S[BATCH * NCH];
__device__ float g_A[BATCH * NCH];
__device__ float g_W[BATCH * NCH];
__device__ float g_P[BATCH * NCH];
__device__ float g_bsum[32];

__device__ __forceinline__ uint32_t smem_u32(const void* p) {
    uint32_t a;
    asm("{ .reg .u64 t; cvta.to.shared.u64 t, %1; cvt.u32.u64 %0, t; }" : "=r"(a) : "l"(p));
    return a;
}
__device__ __forceinline__ void ldm_x4(uint32_t& r0, uint32_t& r1, uint32_t& r2, uint32_t& r3,
                                       uint32_t a) {
    asm volatile("ldmatrix.sync.aligned.m8n8.x4.shared.b16 {%0,%1,%2,%3}, [%4];"
                 : "=r"(r0), "=r"(r1), "=r"(r2), "=r"(r3) : "r"(a));
}
__device__ __forceinline__ void mma16816(float* c, const uint32_t* a, uint32_t b0, uint32_t b1) {
    asm volatile(
        "mma.sync.aligned.m16n8k16.row.col.f32.bf16.bf16.f32 "
        "{%0,%1,%2,%3}, {%4,%5,%6,%7}, {%8,%9}, {%0,%1,%2,%3};"
        : "+f"(c[0]), "+f"(c[1]), "+f"(c[2]), "+f"(c[3])
        : "r"(a[0]), "r"(a[1]), "r"(a[2]), "r"(a[3]), "r"(b0), "r"(b1));
}
// 16B-chunk XOR swizzle: row stride 256B (128 bf16), chunk = 16B unit.
__device__ __forceinline__ uint32_t swz(int row, int c16) {
    return (uint32_t)(row * 256 + ((c16 ^ (row & 7)) << 4));
}

// ======================= prep =======================
__global__ void convert_bf16(const float* __restrict__ F) {
    int i = (blockIdx.x * 256 + threadIdx.x) * 2;
    float2 v = *(const float2*)(F + i);
    *(__nv_bfloat162*)(g_fbf + i) = __floats2bfloat162_rn(v.x, v.y);
}
__global__ void pack_labels(const float* __restrict__ L) {
    int row = blockIdx.x * 256 + threadIdx.x;
    if (row < BATCH) {
        unsigned long long b = 0ull;
        float c = 0.f;
#pragma unroll
        for (int k = 0; k < 50; k++)
            if (L[row * 50 + k] > 0.5f) { b |= (1ull << k); c += 1.f; }
        g_bits[row] = b;
        g_cnt[row] = c;
    }
}

// ======================= main tile kernel =======================
// smem: A tile 32KB @0, B tile 32KB @32768, bitsJ 1KB @65536, cntJ 512B @66560.
#define SMEM_BYTES 67072

__global__ __launch_bounds__(NTHR, 2) void supcon_mma() {
    extern __shared__ char smem[];
    const uint32_t sA = smem_u32(smem);
    const uint32_t sB = sA + 32768;
    unsigned long long* bitsJ = (unsigned long long*)(smem + 65536);
    float* cntJ = (float*)(smem + 66560);

    const int tid = threadIdx.x;
    const int lane = tid & 31, wid = tid >> 5;
    const int wr = wid >> 1, wc = wid & 1;         // warp: 32 rows x 64 cols
    const int jt = blockIdx.x, it = blockIdx.y;
    const int i0 = it * TM, j0 = jt * TN;

    // Load tiles (swizzled 16B chunks). Separate A/B loops -> deeper LDG batching.
    {
        const int row = tid >> 1, c16a = (tid & 1) << 3;   // two 16B chunks per... no:
    }
#pragma unroll
    for (int idx = tid; idx < TM * 16; idx += NTHR) {
        int row = idx >> 4, c16 = idx & 15;
        *(uint4*)(smem + swz(row, c16)) =
            *(const uint4*)(g_fbf + (size_t)(i0 + row) * D + c16 * 8);
    }
#pragma unroll
    for (int idx = tid; idx < TN * 16; idx += NTHR) {
        int row = idx >> 4, c16 = idx & 15;
        *(uint4*)(smem + 32768 + swz(row, c16)) =
            *(const uint4*)(g_fbf + (size_t)(j0 + row) * D + c16 * 8);
    }
#pragma unroll
    for (int x = tid; x < TN; x += NTHR) {
        bitsJ[x] = g_bits[j0 + x];
        cntJ[x] = g_cnt[j0 + x];
    }
    __syncthreads();

    float acc[2][8][4];
#pragma unroll
    for (int m = 0; m < 2; m++)
#pragma unroll
        for (int n = 0; n < 8; n++)
#pragma unroll
            for (int c = 0; c < 4; c++) acc[m][n][c] = 0.f;

    const int lrow = lane & 15, lhalf = lane >> 4;
#pragma unroll 1
    for (int s = 0; s < 8; s++) {       // K = 8 x 16
        uint32_t a[2][4], b[4][4];
#pragma unroll
        for (int m = 0; m < 2; m++)
            ldm_x4(a[m][0], a[m][1], a[m][2], a[m][3],
                   sA + swz(wr * 32 + m * 16 + lrow, 2 * s + lhalf));
#pragma unroll
        for (int g = 0; g < 4; g++)
            ldm_x4(b[g][0], b[g][1], b[g][2], b[g][3],
                   sB + swz(wc * 64 + g * 16 + lrow, 2 * s + lhalf));
#pragma unroll
        for (int m = 0; m < 2; m++)
#pragma unroll
            for (int g = 0; g < 4; g++) {
                mma16816(acc[m][2 * g + 0], a[m], b[g][0], b[g][2]);
                mma16816(acc[m][2 * g + 1], a[m], b[g][1], b[g][3]);
            }
    }

    // ---- fused epilogue: per-row partial stats over this 64-col chunk ----
    const int q = lane >> 2, sub = lane & 3;
    const float invT = 1.0f / 0.07f;
    const int chunk = jt * 2 + wc;

#pragma unroll
    for (int m = 0; m < 2; m++) {
#pragma unroll
        for (int rr = 0; rr < 2; rr++) {
            const int gi = i0 + wr * 32 + m * 16 + rr * 8 + q;
            const unsigned long long bi = g_bits[gi];
            const float ci = g_cnt[gi];

            float mx = -3.4e38f;
#pragma unroll
            for (int n = 0; n < 8; n++) {
                mx = fmaxf(mx, acc[m][n][rr * 2 + 0]);
                mx = fmaxf(mx, acc[m][n][rr * 2 + 1]);
            }
            mx *= invT;   // invT > 0: max commutes with the scale
            mx = fmaxf(mx, __shfl_xor_sync(0xffffffffu, mx, 1));
            mx = fmaxf(mx, __shfl_xor_sync(0xffffffffu, mx, 2));

            float S = 0.f, A = 0.f, W = 0.f, P = 0.f;
#pragma unroll
            for (int n = 0; n < 8; n++) {
#pragma unroll
                for (int e = 0; e < 2; e++) {
                    const int jl = wc * 64 + n * 8 + sub * 2 + e;
                    const float x = acc[m][n][rr * 2 + e] * invT;
                    if (j0 + jl != gi) {
                        S += __expf(x - mx);
                        const float inter = (float)__popcll(bi & bitsJ[jl]);
                        const float tm = fmaxf(ci, cntJ[jl]);
                        const float mu = (inter > 0.f) ? __fdividef(inter, tm) : 0.f;
                        A = fmaf(mu, x, A);
                        W += mu;
                        P += (inter > 0.f) ? 1.f : 0.f;
                    }
                }
            }
#pragma unroll
            for (int o = 1; o < 4; o <<= 1) {
                S += __shfl_xor_sync(0xffffffffu, S, o);
                A += __shfl_xor_sync(0xffffffffu, A, o);
                W += __shfl_xor_sync(0xffffffffu, W, o);
                P += __shfl_xor_sync(0xffffffffu, P, o);
            }
            if (sub == 0) {
                const int o = gi * NCH + chunk;
                g_M[o] = mx; g_S[o] = S; g_A[o] = A; g_W[o] = W; g_P[o] = P;
            }
        }
    }
}

// ======================= reductions =======================
__global__ void row_reduce() {
    const int tid = threadIdx.x;
    const int row = blockIdx.x * 128 + tid;
    float m = -3.4e38f;
#pragma unroll 8
    for (int c = 0; c < NCH; c++) m = fmaxf(m, g_M[row * NCH + c]);
    float S = 0.f, A = 0.f, W = 0.f, P = 0.f;
#pragma unroll 8
    for (int c = 0; c < NCH; c++) {
        const int o = row * NCH + c;
        S += g_S[o] * __expf(g_M[o] - m);
        A += g_A[o];
        W += g_W[o];
        P += g_P[o];
    }
    A -= m * W;
    float v = (A - W * logf(S + 1e-12f)) / (P + 1e-12f);

    __shared__ float red[128];
    red[tid] = v;
    __syncthreads();
#pragma unroll
    for (int s = 64; s > 0; s >>= 1) {
        if (tid < s) red[tid] += red[tid + s];
        __syncthreads();
    }
    if (tid == 0) g_bsum[blockIdx.x] = red[0];
}

__global__ void final_reduce(float* __restrict__ out) {
    float v = g_bsum[threadIdx.x];
#pragma unroll
    for (int o = 16; o > 0; o >>= 1)
        v += __shfl_xor_sync(0xffffffffu, v, o);
    if (threadIdx.x == 0)
        out[0] = -(v * (1.0f / (float)BATCH)) * 0.5f;   // -mean / 2^alpha
}

extern "C" void kernel_launch(void* const* d_in, const int* in_sizes, int n_in,
                              void* d_out, int out_size) {
    const float* F = (const float*)d_in[0];
    const float* L = (const float*)d_in[1];
    if (n_in >= 2 && in_sizes[0] == BATCH * 50 && in_sizes[1] == BATCH * D) {
        const float* t = F; F = L; L = t;
    }
    cudaFuncSetAttribute(supcon_mma, cudaFuncAttributeMaxDynamicSharedMemorySize, SMEM_BYTES);

    convert_bf16<<<BATCH * D / 512, 256>>>(F);
    pack_labels<<<BATCH / 256, 256>>>(L);
    supcon_mma<<<dim3(BATCH / TN, BATCH / TM), NTHR, SMEM_BYTES>>>();
    row_reduce<<<BATCH / 128, 128>>>();
    final_reduce<<<1, 32>>>((float*)d_out);
}

// round 5
// speedup vs baseline: 3.9438x; 1.4569x over previous
#include <cuda_runtime.h>
#include <cuda_bf16.h>
#include <cstdint>

#define BATCH 4096
#define D 128
#define TM 128
#define TN 128
#define NTHR 256
#define NCH 64          // 4096 / 64-col warp chunk

// ---- device scratch (no allocations allowed) ----
__device__ __nv_bfloat16 g_fbf[BATCH * D];   // pre-scaled by sqrt(1/T)
__device__ unsigned long long g_bits[BATCH];
__device__ float g_cnt[BATCH];
__device__ float g_rcnt[BATCH];              // 1/cnt
__device__ float g_diag[BATCH];              // ||f||^2 / T  (row-max shift)
__device__ float g_M[BATCH * NCH];
__device__ float g_S[BATCH * NCH];
__device__ float g_A[BATCH * NCH];
__device__ float g_W[BATCH * NCH];
__device__ float g_P[BATCH * NCH];
__device__ float g_rowv[BATCH];

__device__ __forceinline__ uint32_t smem_u32(const void* p) {
    uint32_t a;
    asm("{ .reg .u64 t; cvta.to.shared.u64 t, %1; cvt.u32.u64 %0, t; }" : "=r"(a) : "l"(p));
    return a;
}
__device__ __forceinline__ void ldm_x4(uint32_t& r0, uint32_t& r1, uint32_t& r2, uint32_t& r3,
                                       uint32_t a) {
    asm volatile("ldmatrix.sync.aligned.m8n8.x4.shared.b16 {%0,%1,%2,%3}, [%4];"
                 : "=r"(r0), "=r"(r1), "=r"(r2), "=r"(r3) : "r"(a));
}
__device__ __forceinline__ void mma16816(float* c, const uint32_t* a, uint32_t b0, uint32_t b1) {
    asm volatile(
        "mma.sync.aligned.m16n8k16.row.col.f32.bf16.bf16.f32 "
        "{%0,%1,%2,%3}, {%4,%5,%6,%7}, {%8,%9}, {%0,%1,%2,%3};"
        : "+f"(c[0]), "+f"(c[1]), "+f"(c[2]), "+f"(c[3])
        : "r"(a[0]), "r"(a[1]), "r"(a[2]), "r"(a[3]), "r"(b0), "r"(b1));
}
// 16B-chunk XOR swizzle: row stride 256B (128 bf16), chunk = 16B unit.
__device__ __forceinline__ uint32_t swz(int row, int c16) {
    return (uint32_t)(row * 256 + ((c16 ^ (row & 7)) << 4));
}

// ======================= prep =======================
// Scale by sqrt(1/T) so the GEMM directly produces logits x = f_i.f_j / T.
#define SQRT_INVT 3.7796447300922722f
#define INVT 14.285714285714286f

__global__ void convert_bf16(const float* __restrict__ F) {
    int i = (blockIdx.x * 256 + threadIdx.x) * 2;
    float2 v = *(const float2*)(F + i);
    *(__nv_bfloat162*)(g_fbf + i) = __floats2bfloat162_rn(v.x * SQRT_INVT, v.y * SQRT_INVT);
}

// Warp per row: pack labels via ballot + compute diag = ||f||^2 / T.
__global__ void prep_rows(const float* __restrict__ F, const float* __restrict__ L) {
    const int lane = threadIdx.x & 31, w = threadIdx.x >> 5;
    const int row = blockIdx.x * 8 + w;

    // labels: 50 floats -> 64-bit mask via two ballots
    float l0 = L[row * 50 + lane];
    float l1 = (lane < 18) ? L[row * 50 + 32 + lane] : 0.f;
    unsigned b0 = __ballot_sync(0xffffffffu, l0 > 0.5f);
    unsigned b1 = __ballot_sync(0xffffffffu, l1 > 0.5f) & 0x3ffffu;
    unsigned long long bits = (unsigned long long)b0 | ((unsigned long long)b1 << 32);
    float cnt = (float)(__popc(b0) + __popc(b1));

    // diag: coalesced float4 per lane (128 floats / 32 lanes)
    float4 v = *(const float4*)(F + (size_t)row * D + lane * 4);
    float d = v.x * v.x + v.y * v.y + v.z * v.z + v.w * v.w;
#pragma unroll
    for (int o = 16; o > 0; o >>= 1) d += __shfl_xor_sync(0xffffffffu, d, o);

    if (lane == 0) {
        g_bits[row] = bits;
        g_cnt[row] = cnt;
        g_rcnt[row] = (cnt > 0.f) ? __fdividef(1.f, cnt) : 0.f;
        g_diag[row] = d * INVT;
    }
}

// ======================= main tile kernel =======================
// smem: A tile 32KB @0, B tile 32KB @32768, bitsJ 1KB @65536, rcJ 512B @66560.
#define SMEM_BYTES 67072

__global__ __launch_bounds__(NTHR, 2) void supcon_mma() {
    extern __shared__ char smem[];
    const uint32_t sA = smem_u32(smem);
    const uint32_t sB = sA + 32768;
    unsigned long long* bitsJ = (unsigned long long*)(smem + 65536);
    float* rcJ = (float*)(smem + 66560);

    const int tid = threadIdx.x;
    const int lane = tid & 31, wid = tid >> 5;
    const int wr = wid >> 1, wc = wid & 1;         // warp: 32 rows x 64 cols
    const int jt = blockIdx.x, it = blockIdx.y;
    const int i0 = it * TM, j0 = jt * TN;

    // Load tiles (swizzled 16B chunks).
#pragma unroll
    for (int idx = tid; idx < TM * 16; idx += NTHR) {
        int row = idx >> 4, c16 = idx & 15;
        *(uint4*)(smem + swz(row, c16)) =
            *(const uint4*)(g_fbf + (size_t)(i0 + row) * D + c16 * 8);
    }
#pragma unroll
    for (int idx = tid; idx < TN * 16; idx += NTHR) {
        int row = idx >> 4, c16 = idx & 15;
        *(uint4*)(smem + 32768 + swz(row, c16)) =
            *(const uint4*)(g_fbf + (size_t)(j0 + row) * D + c16 * 8);
    }
#pragma unroll
    for (int x = tid; x < TN; x += NTHR) {
        bitsJ[x] = g_bits[j0 + x];
        rcJ[x] = g_rcnt[j0 + x];
    }
    __syncthreads();

    float acc[2][8][4];
#pragma unroll
    for (int m = 0; m < 2; m++)
#pragma unroll
        for (int n = 0; n < 8; n++)
#pragma unroll
            for (int c = 0; c < 4; c++) acc[m][n][c] = 0.f;

    const int lrow = lane & 15, lhalf = lane >> 4;
#pragma unroll 1
    for (int s = 0; s < 8; s++) {       // K = 8 x 16
        uint32_t a[2][4], b[4][4];
#pragma unroll
        for (int m = 0; m < 2; m++)
            ldm_x4(a[m][0], a[m][1], a[m][2], a[m][3],
                   sA + swz(wr * 32 + m * 16 + lrow, 2 * s + lhalf));
#pragma unroll
        for (int g = 0; g < 4; g++)
            ldm_x4(b[g][0], b[g][1], b[g][2], b[g][3],
                   sB + swz(wc * 64 + g * 16 + lrow, 2 * s + lhalf));
#pragma unroll
        for (int m = 0; m < 2; m++)
#pragma unroll
            for (int g = 0; g < 4; g++) {
                mma16816(acc[m][2 * g + 0], a[m], b[g][0], b[g][2]);
                mma16816(acc[m][2 * g + 1], a[m], b[g][1], b[g][3]);
            }
    }

    // ---- fused epilogue: per-row partial stats over this 64-col chunk ----
    // acc IS the logit x (inputs pre-scaled by sqrt(1/T)).
    const int q = lane >> 2, sub = lane & 3;
    const int chunk = jt * 2 + wc;

#pragma unroll
    for (int m = 0; m < 2; m++) {
#pragma unroll
        for (int rr = 0; rr < 2; rr++) {
            const int gi = i0 + wr * 32 + m * 16 + rr * 8 + q;
            const unsigned long long bi = g_bits[gi];
            const float rci = g_rcnt[gi];
            const float di = g_diag[gi];

            float mx = -3.4e38f;
#pragma unroll
            for (int n = 0; n < 8; n++) {
                mx = fmaxf(mx, acc[m][n][rr * 2 + 0]);
                mx = fmaxf(mx, acc[m][n][rr * 2 + 1]);
            }
            mx = fmaxf(mx, __shfl_xor_sync(0xffffffffu, mx, 1));
            mx = fmaxf(mx, __shfl_xor_sync(0xffffffffu, mx, 2));
            const float sh = fmaxf(di, mx);   // >= true chunk max; diag-dominant shift

            float S = 0.f, A = 0.f, W = 0.f, P = 0.f;
#pragma unroll
            for (int n = 0; n < 8; n++) {
#pragma unroll
                for (int e = 0; e < 2; e++) {
                    const int jl = wc * 64 + n * 8 + sub * 2 + e;
                    const float x = acc[m][n][rr * 2 + e];
                    if (j0 + jl != gi) {
                        // exp(z) for z <= -60 contributes < 9e-27 << eps: skip MUFU.
                        const float z = x - sh;
                        if (z > -60.f) S += __expf(z);
                        const float inter = (float)__popcll(bi & bitsJ[jl]);
                        if (inter > 0.f) {
                            // 1/max(ci,cj) == min(1/ci, 1/cj)
                            const float mu = inter * fminf(rci, rcJ[jl]);
                            A = fmaf(mu, x, A);
                            W += mu;
                            P += 1.f;
                        }
                    }
                }
            }
#pragma unroll
            for (int o = 1; o < 4; o <<= 1) {
                S += __shfl_xor_sync(0xffffffffu, S, o);
                A += __shfl_xor_sync(0xffffffffu, A, o);
                W += __shfl_xor_sync(0xffffffffu, W, o);
                P += __shfl_xor_sync(0xffffffffu, P, o);
            }
            if (sub == 0) {
                const int o = gi * NCH + chunk;
                g_M[o] = sh; g_S[o] = S; g_A[o] = A; g_W[o] = W; g_P[o] = P;
            }
        }
    }
}

// ======================= reductions =======================
// Warp per row: coalesced chunk loads + shuffle LSE merge.
__global__ void row_reduce() {
    const int lane = threadIdx.x & 31, w = threadIdx.x >> 5;
    const int row = blockIdx.x * 8 + w;
    const int o0 = row * NCH + lane, o1 = o0 + 32;

    const float m0 = g_M[o0], m1 = g_M[o1];
    float m = fmaxf(m0, m1);
    float S = g_S[o0] * __expf(m0 - m) + g_S[o1] * __expf(m1 - m);
    float A = g_A[o0] + g_A[o1];
    float W = g_W[o0] + g_W[o1];
    float P = g_P[o0] + g_P[o1];

#pragma unroll
    for (int o = 16; o > 0; o >>= 1) {
        const float mo = __shfl_xor_sync(0xffffffffu, m, o);
        const float So = __shfl_xor_sync(0xffffffffu, S, o);
        const float mn = fmaxf(m, mo);
        S = S * __expf(m - mn) + So * __expf(mo - mn);
        m = mn;
        A += __shfl_xor_sync(0xffffffffu, A, o);
        W += __shfl_xor_sync(0xffffffffu, W, o);
        P += __shfl_xor_sync(0xffffffffu, P, o);
    }
    if (lane == 0) {
        A -= m * W;
        g_rowv[row] = (A - W * logf(S + 1e-12f)) / (P + 1e-12f);
    }
}

__global__ void final_reduce(float* __restrict__ out) {
    const int t = threadIdx.x;
    float v = g_rowv[t] + g_rowv[t + 1024] + g_rowv[t + 2048] + g_rowv[t + 3072];
    __shared__ float red[1024];
    red[t] = v;
    __syncthreads();
#pragma unroll
    for (int s = 512; s >= 32; s >>= 1) {
        if (t < s) red[t] += red[t + s];
        __syncthreads();
    }
    if (t < 32) {
        float x = red[t];
#pragma unroll
        for (int o = 16; o > 0; o >>= 1)
            x += __shfl_xor_sync(0xffffffffu, x, o);
        if (t == 0)
            out[0] = -(x * (1.0f / (float)BATCH)) * 0.5f;   // -mean / 2^alpha
    }
}

extern "C" void kernel_launch(void* const* d_in, const int* in_sizes, int n_in,
                              void* d_out, int out_size) {
    const float* F = (const float*)d_in[0];
    const float* L = (const float*)d_in[1];
    if (n_in >= 2 && in_sizes[0] == BATCH * 50 && in_sizes[1] == BATCH * D) {
        const float* t = F; F = L; L = t;
    }
    cudaFuncSetAttribute(supcon_mma, cudaFuncAttributeMaxDynamicSharedMemorySize, SMEM_BYTES);

    convert_bf16<<<BATCH * D / 512, 256>>>(F);
    prep_rows<<<BATCH / 8, 256>>>(F, L);
    supcon_mma<<<dim3(BATCH / TN, BATCH / TM), NTHR, SMEM_BYTES>>>();
    row_reduce<<<BATCH / 8, 256>>>();
    final_reduce<<<1, 1024>>>((float*)d_out);
}

// round 7
// speedup vs baseline: 4.5589x; 1.1560x over previous
#include <cuda_runtime.h>
#include <cuda_bf16.h>
#include <cstdint>

#define BATCH 4096
#define D 128
#define TM 128
#define TN 128
#define NTHR 256
#define NCH 64          // 4096 / 64-col warp chunk
#define NPART 512

// ---- device scratch (no allocations allowed) ----
__device__ __nv_bfloat16 g_fbf[BATCH * D];   // pre-scaled by sqrt(1/T)
__device__ unsigned long long g_bits[BATCH];
__device__ float g_rcnt[BATCH];              // 1/cnt (0 if cnt==0)
__device__ float g_diag[BATCH];              // ||f||^2 / T
__device__ float g_M[BATCH * NCH];
__device__ float g_S[BATCH * NCH];
__device__ float g_A[BATCH * NCH];
__device__ float g_W[BATCH * NCH];
__device__ float g_P[BATCH * NCH];
__device__ float g_part[NPART];
__device__ int g_sem;

__device__ __forceinline__ uint32_t smem_u32(const void* p) {
    uint32_t a;
    asm("{ .reg .u64 t; cvta.to.shared.u64 t, %1; cvt.u32.u64 %0, t; }" : "=r"(a) : "l"(p));
    return a;
}
__device__ __forceinline__ void ldm_x4(uint32_t& r0, uint32_t& r1, uint32_t& r2, uint32_t& r3,
                                       uint32_t a) {
    asm volatile("ldmatrix.sync.aligned.m8n8.x4.shared.b16 {%0,%1,%2,%3}, [%4];"
                 : "=r"(r0), "=r"(r1), "=r"(r2), "=r"(r3) : "r"(a));
}
__device__ __forceinline__ void mma16816(float* c, const uint32_t* a, uint32_t b0, uint32_t b1) {
    asm volatile(
        "mma.sync.aligned.m16n8k16.row.col.f32.bf16.bf16.f32 "
        "{%0,%1,%2,%3}, {%4,%5,%6,%7}, {%8,%9}, {%0,%1,%2,%3};"
        : "+f"(c[0]), "+f"(c[1]), "+f"(c[2]), "+f"(c[3])
        : "r"(a[0]), "r"(a[1]), "r"(a[2]), "r"(a[3]), "r"(b0), "r"(b1));
}
__device__ __forceinline__ uint32_t swz(int row, int c16) {
    return (uint32_t)(row * 256 + ((c16 ^ (row & 7)) << 4));
}

#define SQRT_INVT 3.7796447300922722f
#define INVT 14.285714285714286f

// ======================= k1: fused prep (convert + labels + diag) =======================
__global__ void prep_rows(const float* __restrict__ F, const float* __restrict__ L) {
    const int lane = threadIdx.x & 31, w = threadIdx.x >> 5;
    const int row = blockIdx.x * 8 + w;

    // one pass over F row: norm + scaled bf16 conversion
    float4 v = *(const float4*)(F + (size_t)row * D + lane * 4);
    float d = v.x * v.x + v.y * v.y + v.z * v.z + v.w * v.w;
#pragma unroll
    for (int o = 16; o > 0; o >>= 1) d += __shfl_xor_sync(0xffffffffu, d, o);

    __nv_bfloat162* dst = (__nv_bfloat162*)(g_fbf + (size_t)row * D + lane * 4);
    dst[0] = __floats2bfloat162_rn(v.x * SQRT_INVT, v.y * SQRT_INVT);
    dst[1] = __floats2bfloat162_rn(v.z * SQRT_INVT, v.w * SQRT_INVT);

    // labels: 50 floats -> 64-bit mask via two ballots
    float l0 = L[row * 50 + lane];
    float l1 = (lane < 18) ? L[row * 50 + 32 + lane] : 0.f;
    unsigned b0 = __ballot_sync(0xffffffffu, l0 > 0.5f);
    unsigned b1 = __ballot_sync(0xffffffffu, l1 > 0.5f) & 0x3ffffu;

    if (lane == 0) {
        unsigned long long bits = (unsigned long long)b0 | ((unsigned long long)b1 << 32);
        float cnt = (float)(__popc(b0) + __popc(b1));
        g_bits[row] = bits;
        g_rcnt[row] = (cnt > 0.f) ? __fdividef(1.f, cnt) : 0.f;
        g_diag[row] = d * INVT;
    }
}

// k2/k3: tiny resets (also splitters so supcon_mma is the 4th launch for ncu)
__global__ void reset_sem() { if (threadIdx.x == 0) g_sem = 0; }
__global__ void reset_part() { g_part[blockIdx.x * 32 + threadIdx.x] = 0.f; }

// ======================= k4: main tile kernel =======================
// smem: A tile 32KB @0, B tile 32KB @32768, bitsJ 1KB @65536, rcJ 512B @66560.
#define SMEM_BYTES 67072

__global__ __launch_bounds__(NTHR, 2) void supcon_mma() {
    extern __shared__ char smem[];
    const uint32_t sA = smem_u32(smem);
    const uint32_t sB = sA + 32768;
    unsigned long long* bitsJ = (unsigned long long*)(smem + 65536);
    float* rcJ = (float*)(smem + 66560);

    const int tid = threadIdx.x;
    const int lane = tid & 31, wid = tid >> 5;
    const int wr = wid >> 1, wc = wid & 1;         // warp: 32 rows x 64 cols
    const int jt = blockIdx.x, it = blockIdx.y;
    const int i0 = it * TM, j0 = jt * TN;

#pragma unroll
    for (int idx = tid; idx < TM * 16; idx += NTHR) {
        int row = idx >> 4, c16 = idx & 15;
        *(uint4*)(smem + swz(row, c16)) =
            *(const uint4*)(g_fbf + (size_t)(i0 + row) * D + c16 * 8);
    }
#pragma unroll
    for (int idx = tid; idx < TN * 16; idx += NTHR) {
        int row = idx >> 4, c16 = idx & 15;
        *(uint4*)(smem + 32768 + swz(row, c16)) =
            *(const uint4*)(g_fbf + (size_t)(j0 + row) * D + c16 * 8);
    }
#pragma unroll
    for (int x = tid; x < TN; x += NTHR) {
        bitsJ[x] = g_bits[j0 + x];
        rcJ[x] = g_rcnt[j0 + x];
    }
    __syncthreads();

    float acc[2][8][4];
#pragma unroll
    for (int m = 0; m < 2; m++)
#pragma unroll
        for (int n = 0; n < 8; n++)
#pragma unroll
            for (int c = 0; c < 4; c++) acc[m][n][c] = 0.f;

    const int lrow = lane & 15, lhalf = lane >> 4;
#pragma unroll 1
    for (int s = 0; s < 8; s++) {       // K = 8 x 16
        uint32_t a[2][4], b[4][4];
#pragma unroll
        for (int m = 0; m < 2; m++)
            ldm_x4(a[m][0], a[m][1], a[m][2], a[m][3],
                   sA + swz(wr * 32 + m * 16 + lrow, 2 * s + lhalf));
#pragma unroll
        for (int g = 0; g < 4; g++)
            ldm_x4(b[g][0], b[g][1], b[g][2], b[g][3],
                   sB + swz(wc * 64 + g * 16 + lrow, 2 * s + lhalf));
#pragma unroll
        for (int m = 0; m < 2; m++)
#pragma unroll
            for (int g = 0; g < 4; g++) {
                mma16816(acc[m][2 * g + 0], a[m], b[g][0], b[g][2]);
                mma16816(acc[m][2 * g + 1], a[m], b[g][1], b[g][3]);
            }
    }

    // ---- fused branchless epilogue ----
    const int q = lane >> 2, sub = lane & 3;
    const int chunk = jt * 2 + wc;
    const unsigned long long* bJ = bitsJ + wc * 64;
    const float* rJ = rcJ + wc * 64;

#pragma unroll
    for (int m = 0; m < 2; m++) {
#pragma unroll
        for (int rr = 0; rr < 2; rr++) {
            const int gi = i0 + wr * 32 + m * 16 + rr * 8 + q;
            const unsigned long long bi = g_bits[gi];
            const float rci = g_rcnt[gi];
            const float di = g_diag[gi];
            const int dcol = gi - j0 - wc * 64;   // local diag col, or out of [0,64)

            float mx = -3.4e38f;
#pragma unroll
            for (int n = 0; n < 8; n++) {
                mx = fmaxf(mx, acc[m][n][rr * 2 + 0]);
                mx = fmaxf(mx, acc[m][n][rr * 2 + 1]);
            }
            mx = fmaxf(mx, __shfl_xor_sync(0xffffffffu, mx, 1));
            mx = fmaxf(mx, __shfl_xor_sync(0xffffffffu, mx, 2));
            const float sh = fmaxf(di, mx);

            float S = 0.f, A = 0.f, W = 0.f, P = 0.f;
#pragma unroll
            for (int n = 0; n < 8; n++) {
#pragma unroll
                for (int e = 0; e < 2; e++) {
                    const int lc = n * 8 + sub * 2 + e;
                    const float x = acc[m][n][rr * 2 + e];
                    const bool dg = (lc == dcol);
                    const float z = dg ? -1e30f : (x - sh);
                    float inter = (float)__popcll(bi & bJ[lc]);
                    inter = dg ? 0.f : inter;
                    if (z > -60.f) S += __expf(z);    // predicated; rarely taken
                    const float mu = inter * fminf(rci, rJ[lc]);
                    A = fmaf(mu, x, A);
                    W += mu;
                    P += (inter > 0.f) ? 1.f : 0.f;
                }
            }
#pragma unroll
            for (int o = 1; o < 4; o <<= 1) {
                S += __shfl_xor_sync(0xffffffffu, S, o);
                A += __shfl_xor_sync(0xffffffffu, A, o);
                W += __shfl_xor_sync(0xffffffffu, W, o);
                P += __shfl_xor_sync(0xffffffffu, P, o);
            }
            if (sub == 0) {
                const int o = gi * NCH + chunk;
                g_M[o] = sh; g_S[o] = S; g_A[o] = A; g_W[o] = W; g_P[o] = P;
            }
        }
    }
}

// ======================= k5: fused row-merge + final reduction =======================
__global__ void reduce_all(float* __restrict__ out) {
    const int lane = threadIdx.x & 31, w = threadIdx.x >> 5;
    const int row = blockIdx.x * 8 + w;
    const int o0 = row * NCH + lane, o1 = o0 + 32;

    const float m0 = g_M[o0], m1 = g_M[o1];
    float m = fmaxf(m0, m1);
    float S = g_S[o0] * __expf(m0 - m) + g_S[o1] * __expf(m1 - m);
    float A = g_A[o0] + g_A[o1];
    float W = g_W[o0] + g_W[o1];
    float P = g_P[o0] + g_P[o1];

#pragma unroll
    for (int o = 16; o > 0; o >>= 1) {
        const float mo = __shfl_xor_sync(0xffffffffu, m, o);
        const float So = __shfl_xor_sync(0xffffffffu, S, o);
        const float mn = fmaxf(m, mo);
        S = S * __expf(m - mn) + So * __expf(mo - mn);
        m = mn;
        A += __shfl_xor_sync(0xffffffffu, A, o);
        W += __shfl_xor_sync(0xffffffffu, W, o);
        P += __shfl_xor_sync(0xffffffffu, P, o);
    }

    __shared__ float sv[8];
    if (lane == 0) {
        A -= m * W;
        sv[w] = (A - W * logf(S + 1e-12f)) / (P + 1e-12f);
    }
    __syncthreads();

    if (w == 0) {
        float t = (lane < 8) ? sv[lane] : 0.f;
#pragma unroll
        for (int o = 4; o > 0; o >>= 1) t += __shfl_xor_sync(0xffffffffu, t, o);

        int is_last = 0;
        if (lane == 0) {
            g_part[blockIdx.x] = t;
            __threadfence();
            is_last = (atomicAdd(&g_sem, 1) == NPART - 1) ? 1 : 0;
        }
        is_last = __shfl_sync(0xffffffffu, is_last, 0);
        if (is_last) {
            __threadfence();
            float s = 0.f;
#pragma unroll
            for (int k = 0; k < NPART / 32; k++)   // fixed order -> deterministic
                s += g_part[lane + k * 32];
#pragma unroll
            for (int o = 16; o > 0; o >>= 1)
                s += __shfl_xor_sync(0xffffffffu, s, o);
            if (lane == 0)
                out[0] = -(s * (1.0f / (float)BATCH)) * 0.5f;   // -mean / 2^alpha
        }
    }
}

extern "C" void kernel_launch(void* const* d_in, const int* in_sizes, int n_in,
                              void* d_out, int out_size) {
    const float* F = (const float*)d_in[0];
    const float* L = (const float*)d_in[1];
    if (n_in >= 2 && in_sizes[0] == BATCH * 50 && in_sizes[1] == BATCH * D) {
        const float* t = F; F = L; L = t;
    }
    cudaFuncSetAttribute(supcon_mma, cudaFuncAttributeMaxDynamicSharedMemorySize, SMEM_BYTES);

    prep_rows<<<BATCH / 8, 256>>>(F, L);                      // #1
    reset_sem<<<1, 32>>>();                                   // #2
    reset_part<<<NPART / 32, 32>>>();                         // #3
    supcon_mma<<<dim3(BATCH / TN, BATCH / TM), NTHR, SMEM_BYTES>>>();  // #4 (ncu slot)
    reduce_all<<<NPART, 256>>>((float*)d_out);                // #5
}

// round 8
// speedup vs baseline: 5.0866x; 1.1158x over previous
#include <cuda_runtime.h>
#include <cuda_bf16.h>
#include <cstdint>

#define BATCH 4096
#define D 128
#define TM 128
#define TN 128
#define NTHR 256
#define NTILE 528       // 32*33/2 upper-triangular tiles
#define NPART 512

// ---- device scratch (no allocations allowed) ----
__device__ __nv_bfloat16 g_fbf[BATCH * D];   // pre-scaled by sqrt(1/T)
__device__ unsigned long long g_bits[BATCH];
__device__ float g_rcnt[BATCH];              // 1/cnt (0 if cnt==0)
__device__ float g_diag[BATCH];              // ||f||^2 / T  == row shift m
__device__ float g_S[BATCH * 64];            // row partials, chunk = jt*2+wc
__device__ float g_A[BATCH * 64];
__device__ float g_W[BATCH * 64];
__device__ float g_P[BATCH * 64];
__device__ float g_cS[BATCH * 128];          // col partials, chunk = it*4+wr
__device__ float g_cA[BATCH * 128];
__device__ float g_cW[BATCH * 128];
__device__ float g_cP[BATCH * 128];
__device__ float g_part[NPART];
__device__ int g_sem;

__device__ __forceinline__ uint32_t smem_u32(const void* p) {
    uint32_t a;
    asm("{ .reg .u64 t; cvta.to.shared.u64 t, %1; cvt.u32.u64 %0, t; }" : "=r"(a) : "l"(p));
    return a;
}
__device__ __forceinline__ void ldm_x4(uint32_t& r0, uint32_t& r1, uint32_t& r2, uint32_t& r3,
                                       uint32_t a) {
    asm volatile("ldmatrix.sync.aligned.m8n8.x4.shared.b16 {%0,%1,%2,%3}, [%4];"
                 : "=r"(r0), "=r"(r1), "=r"(r2), "=r"(r3) : "r"(a));
}
__device__ __forceinline__ void mma16816(float* c, const uint32_t* a, uint32_t b0, uint32_t b1) {
    asm volatile(
        "mma.sync.aligned.m16n8k16.row.col.f32.bf16.bf16.f32 "
        "{%0,%1,%2,%3}, {%4,%5,%6,%7}, {%8,%9}, {%0,%1,%2,%3};"
        : "+f"(c[0]), "+f"(c[1]), "+f"(c[2]), "+f"(c[3])
        : "r"(a[0]), "r"(a[1]), "r"(a[2]), "r"(a[3]), "r"(b0), "r"(b1));
}
__device__ __forceinline__ uint32_t swz(int row, int c16) {
    return (uint32_t)(row * 256 + ((c16 ^ (row & 7)) << 4));
}

#define SQRT_INVT 3.7796447300922722f
#define INVT 14.285714285714286f

// ======================= k1: fused prep (convert + labels + diag + sem reset) ============
__global__ void prep_rows(const float* __restrict__ F, const float* __restrict__ L) {
    const int lane = threadIdx.x & 31, w = threadIdx.x >> 5;
    const int row = blockIdx.x * 8 + w;
    if (blockIdx.x == 0 && threadIdx.x == 0) g_sem = 0;

    float4 v = *(const float4*)(F + (size_t)row * D + lane * 4);
    float d = v.x * v.x + v.y * v.y + v.z * v.z + v.w * v.w;
#pragma unroll
    for (int o = 16; o > 0; o >>= 1) d += __shfl_xor_sync(0xffffffffu, d, o);

    __nv_bfloat162* dst = (__nv_bfloat162*)(g_fbf + (size_t)row * D + lane * 4);
    dst[0] = __floats2bfloat162_rn(v.x * SQRT_INVT, v.y * SQRT_INVT);
    dst[1] = __floats2bfloat162_rn(v.z * SQRT_INVT, v.w * SQRT_INVT);

    float l0 = L[row * 50 + lane];
    float l1 = (lane < 18) ? L[row * 50 + 32 + lane] : 0.f;
    unsigned b0 = __ballot_sync(0xffffffffu, l0 > 0.5f);
    unsigned b1 = __ballot_sync(0xffffffffu, l1 > 0.5f) & 0x3ffffu;

    if (lane == 0) {
        unsigned long long bits = (unsigned long long)b0 | ((unsigned long long)b1 << 32);
        float cnt = (float)(__popc(b0) + __popc(b1));
        g_bits[row] = bits;
        g_rcnt[row] = (cnt > 0.f) ? __fdividef(1.f, cnt) : 0.f;
        g_diag[row] = d * INVT;
    }
}

// ======================= k2: main tile kernel (upper triangle only) =======================
// smem: A 32KB @0, B 32KB @32768, bitsJ 1KB @65536, rcJ 512B @66560, dJ 512B @67072.
#define SMEM_BYTES 67584

__global__ __launch_bounds__(NTHR, 2) void supcon_mma() {
    extern __shared__ char smem[];
    const uint32_t sA = smem_u32(smem);
    const uint32_t sB = sA + 32768;
    unsigned long long* bitsJ = (unsigned long long*)(smem + 65536);
    float* rcJ = (float*)(smem + 66560);
    float* dJ = (float*)(smem + 67072);

    // triangular decode: blockIdx.x -> (it, jt), it <= jt
    int t = blockIdx.x, it = 0, rem = 32;
    while (t >= rem) { t -= rem; it++; rem--; }
    const int jt = it + t;

    const int tid = threadIdx.x;
    const int lane = tid & 31, wid = tid >> 5;
    const int wr = wid >> 1, wc = wid & 1;         // warp: 32 rows x 64 cols
    const int i0 = it * TM, j0 = jt * TN;

#pragma unroll
    for (int idx = tid; idx < TM * 16; idx += NTHR) {
        int row = idx >> 4, c16 = idx & 15;
        *(uint4*)(smem + swz(row, c16)) =
            *(const uint4*)(g_fbf + (size_t)(i0 + row) * D + c16 * 8);
    }
#pragma unroll
    for (int idx = tid; idx < TN * 16; idx += NTHR) {
        int row = idx >> 4, c16 = idx & 15;
        *(uint4*)(smem + 32768 + swz(row, c16)) =
            *(const uint4*)(g_fbf + (size_t)(j0 + row) * D + c16 * 8);
    }
#pragma unroll
    for (int x = tid; x < TN; x += NTHR) {
        bitsJ[x] = g_bits[j0 + x];
        rcJ[x] = g_rcnt[j0 + x];
        dJ[x] = g_diag[j0 + x];
    }
    __syncthreads();

    float acc[2][8][4];
#pragma unroll
    for (int m = 0; m < 2; m++)
#pragma unroll
        for (int n = 0; n < 8; n++)
#pragma unroll
            for (int c = 0; c < 4; c++) acc[m][n][c] = 0.f;

    const int lrow = lane & 15, lhalf = lane >> 4;
#pragma unroll 1
    for (int s = 0; s < 8; s++) {       // K = 8 x 16
        uint32_t a[2][4], b[4][4];
#pragma unroll
        for (int m = 0; m < 2; m++)
            ldm_x4(a[m][0], a[m][1], a[m][2], a[m][3],
                   sA + swz(wr * 32 + m * 16 + lrow, 2 * s + lhalf));
#pragma unroll
        for (int g = 0; g < 4; g++)
            ldm_x4(b[g][0], b[g][1], b[g][2], b[g][3],
                   sB + swz(wc * 64 + g * 16 + lrow, 2 * s + lhalf));
#pragma unroll
        for (int m = 0; m < 2; m++)
#pragma unroll
            for (int g = 0; g < 4; g++) {
                mma16816(acc[m][2 * g + 0], a[m], b[g][0], b[g][2]);
                mma16816(acc[m][2 * g + 1], a[m], b[g][1], b[g][3]);
            }
    }

    // ---- fused row + column epilogue (shift = exact diag, no max tracking) ----
    const int q = lane >> 2, sub = lane & 3;
    const bool offd = (it != jt);
    const int colbase = wc * 64;

    float rS[4], rA[4], rW[4], rP[4], di4[4], rci4[4];
    unsigned long long bi4[4];
    int gi4[4];
#pragma unroll
    for (int g = 0; g < 4; g++) {
        const int m = g >> 1, rr = g & 1;
        const int gi = i0 + wr * 32 + m * 16 + rr * 8 + q;
        gi4[g] = gi; bi4[g] = g_bits[gi]; rci4[g] = g_rcnt[gi]; di4[g] = g_diag[gi];
        rS[g] = rA[g] = rW[g] = rP[g] = 0.f;
    }

#pragma unroll
    for (int n = 0; n < 8; n++) {
#pragma unroll
        for (int e = 0; e < 2; e++) {
            const int jl = n * 8 + sub * 2 + e;
            const int gj = j0 + colbase + jl;
            const unsigned long long bj = bitsJ[colbase + jl];
            const float rcj = rcJ[colbase + jl];
            const float dj = dJ[colbase + jl];
            float cS = 0.f, cA = 0.f, cW = 0.f, cP = 0.f;
#pragma unroll
            for (int g = 0; g < 4; g++) {
                const int m = g >> 1, rr = g & 1;
                const float x = acc[m][n][rr * 2 + e];
                const bool dg = (gi4[g] == gj);
                float inter = (float)__popcll(bi4[g] & bj);
                inter = dg ? 0.f : inter;
                const float mu = inter * fminf(rci4[g], rcj);
                const float tv = mu * x;
                rA[g] += tv; cA += tv;
                rW[g] += mu; cW += mu;
                const float one = (inter > 0.f) ? 1.f : 0.f;
                rP[g] += one; cP += one;
                const float zr = dg ? -1e30f : x - di4[g];
                if (zr > -60.f) rS[g] += __expf(zr);     // contributes < 9e-27 below cutoff
                const float zc = dg ? -1e30f : x - dj;
                if (zc > -60.f) cS += __expf(zc);
            }
            if (offd) {
#pragma unroll
                for (int o = 4; o <= 16; o <<= 1) {
                    cS += __shfl_xor_sync(0xffffffffu, cS, o);
                    cA += __shfl_xor_sync(0xffffffffu, cA, o);
                    cW += __shfl_xor_sync(0xffffffffu, cW, o);
                    cP += __shfl_xor_sync(0xffffffffu, cP, o);
                }
                if (q == 0) {
                    const int slot = gj * 128 + it * 4 + wr;
                    g_cS[slot] = cS; g_cA[slot] = cA; g_cW[slot] = cW; g_cP[slot] = cP;
                }
            }
        }
    }

#pragma unroll
    for (int g = 0; g < 4; g++) {
        float S = rS[g], A = rA[g], W = rW[g], P = rP[g];
#pragma unroll
        for (int o = 1; o < 4; o <<= 1) {
            S += __shfl_xor_sync(0xffffffffu, S, o);
            A += __shfl_xor_sync(0xffffffffu, A, o);
            W += __shfl_xor_sync(0xffffffffu, W, o);
            P += __shfl_xor_sync(0xffffffffu, P, o);
        }
        if (sub == 0) {
            const int o2 = gi4[g] * 64 + jt * 2 + wc;
            g_S[o2] = S; g_A[o2] = A; g_W[o2] = W; g_P[o2] = P;
        }
    }
}

// ======================= k3: reduce (plain sums — all partials share shift di) ============
__global__ void reduce_all(float* __restrict__ out) {
    const int lane = threadIdx.x & 31, w = threadIdx.x >> 5;
    const int row = blockIdx.x * 8 + w;
    const int b = row >> 7;

    float S = 0.f, A = 0.f, W = 0.f, P = 0.f;
    for (int c = 2 * b + lane; c < 64; c += 32) {    // valid row chunks
        const int o = row * 64 + c;
        S += g_S[o]; A += g_A[o]; W += g_W[o]; P += g_P[o];
    }
    for (int c = lane; c < 4 * b; c += 32) {         // valid col chunks
        const int o = row * 128 + c;
        S += g_cS[o]; A += g_cA[o]; W += g_cW[o]; P += g_cP[o];
    }
#pragma unroll
    for (int o = 16; o > 0; o >>= 1) {
        S += __shfl_xor_sync(0xffffffffu, S, o);
        A += __shfl_xor_sync(0xffffffffu, A, o);
        W += __shfl_xor_sync(0xffffffffu, W, o);
        P += __shfl_xor_sync(0xffffffffu, P, o);
    }

    __shared__ float sv[8];
    if (lane == 0) {
        const float di = g_diag[row];
        sv[w] = (A - di * W - W * logf(S + 1e-12f)) / (P + 1e-12f);
    }
    __syncthreads();

    if (w == 0) {
        float t = (lane < 8) ? sv[lane] : 0.f;
#pragma unroll
        for (int o = 4; o > 0; o >>= 1) t += __shfl_xor_sync(0xffffffffu, t, o);

        int is_last = 0;
        if (lane == 0) {
            g_part[blockIdx.x] = t;
            __threadfence();
            is_last = (atomicAdd(&g_sem, 1) == NPART - 1) ? 1 : 0;
        }
        is_last = __shfl_sync(0xffffffffu, is_last, 0);
        if (is_last) {
            __threadfence();
            float s = 0.f;
#pragma unroll
            for (int k = 0; k < NPART / 32; k++)   // fixed order -> deterministic
                s += g_part[lane + k * 32];
#pragma unroll
            for (int o = 16; o > 0; o >>= 1)
                s += __shfl_xor_sync(0xffffffffu, s, o);
            if (lane == 0)
                out[0] = -(s * (1.0f / (float)BATCH)) * 0.5f;   // -mean / 2^alpha
        }
    }
}

extern "C" void kernel_launch(void* const* d_in, const int* in_sizes, int n_in,
                              void* d_out, int out_size) {
    const float* F = (const float*)d_in[0];
    const float* L = (const float*)d_in[1];
    if (n_in >= 2 && in_sizes[0] == BATCH * 50 && in_sizes[1] == BATCH * D) {
        const float* t = F; F = L; L = t;
    }
    cudaFuncSetAttribute(supcon_mma, cudaFuncAttributeMaxDynamicSharedMemorySize, SMEM_BYTES);

    prep_rows<<<BATCH / 8, 256>>>(F, L);
    supcon_mma<<<NTILE, NTHR, SMEM_BYTES>>>();
    reduce_all<<<NPART, 256>>>((float*)d_out);
}

// round 9
// speedup vs baseline: 5.6012x; 1.1012x over previous
#include <cuda_runtime.h>
#include <cuda_bf16.h>
#include <cstdint>

#define BATCH 4096
#define D 128
#define TM 128
#define TN 128
#define NTHR 256
#define NTILE 528       // 496 strict-upper + 32 diag
#define NPERS 296       // 2 CTAs x 148 SMs
#define NPART 512

// ---- device scratch (no allocations allowed) ----
__device__ __nv_bfloat16 g_fbf[BATCH * D];   // pre-scaled by sqrt(1/T)
__device__ unsigned long long g_bits[BATCH];
__device__ float g_rcnt[BATCH];              // 1/cnt (0 if cnt==0)
__device__ float g_diag[BATCH];              // ||f||^2 / T == row shift
__device__ float4 g_row4[BATCH * 64];        // {S,A,W,P} row partials, chunk=jt*2+wc
__device__ float4 g_col4[BATCH * 128];       // col partials, chunk=it*4+wr
__device__ float g_part[NPART];
__device__ int g_sem;
__device__ int g_tick;

__device__ __forceinline__ uint32_t smem_u32(const void* p) {
    uint32_t a;
    asm("{ .reg .u64 t; cvta.to.shared.u64 t, %1; cvt.u32.u64 %0, t; }" : "=r"(a) : "l"(p));
    return a;
}
__device__ __forceinline__ void ldm_x4(uint32_t& r0, uint32_t& r1, uint32_t& r2, uint32_t& r3,
                                       uint32_t a) {
    asm volatile("ldmatrix.sync.aligned.m8n8.x4.shared.b16 {%0,%1,%2,%3}, [%4];"
                 : "=r"(r0), "=r"(r1), "=r"(r2), "=r"(r3) : "r"(a));
}
__device__ __forceinline__ void mma16816(float* c, const uint32_t* a, uint32_t b0, uint32_t b1) {
    asm volatile(
        "mma.sync.aligned.m16n8k16.row.col.f32.bf16.bf16.f32 "
        "{%0,%1,%2,%3}, {%4,%5,%6,%7}, {%8,%9}, {%0,%1,%2,%3};"
        : "+f"(c[0]), "+f"(c[1]), "+f"(c[2]), "+f"(c[3])
        : "r"(a[0]), "r"(a[1]), "r"(a[2]), "r"(a[3]), "r"(b0), "r"(b1));
}
__device__ __forceinline__ uint32_t swz(int row, int c16) {
    return (uint32_t)(row * 256 + ((c16 ^ (row & 7)) << 4));
}

#define SQRT_INVT 3.7796447300922722f
#define INVT 14.285714285714286f

// ======================= k1: fused prep =======================
__global__ void prep_rows(const float* __restrict__ F, const float* __restrict__ L) {
    const int lane = threadIdx.x & 31, w = threadIdx.x >> 5;
    const int row = blockIdx.x * 8 + w;
    if (blockIdx.x == 0 && threadIdx.x == 0) { g_sem = 0; g_tick = 0; }

    float4 v = *(const float4*)(F + (size_t)row * D + lane * 4);
    float d = v.x * v.x + v.y * v.y + v.z * v.z + v.w * v.w;
#pragma unroll
    for (int o = 16; o > 0; o >>= 1) d += __shfl_xor_sync(0xffffffffu, d, o);

    __nv_bfloat162* dst = (__nv_bfloat162*)(g_fbf + (size_t)row * D + lane * 4);
    dst[0] = __floats2bfloat162_rn(v.x * SQRT_INVT, v.y * SQRT_INVT);
    dst[1] = __floats2bfloat162_rn(v.z * SQRT_INVT, v.w * SQRT_INVT);

    float l0 = L[row * 50 + lane];
    float l1 = (lane < 18) ? L[row * 50 + 32 + lane] : 0.f;
    unsigned b0 = __ballot_sync(0xffffffffu, l0 > 0.5f);
    unsigned b1 = __ballot_sync(0xffffffffu, l1 > 0.5f) & 0x3ffffu;

    if (lane == 0) {
        unsigned long long bits = (unsigned long long)b0 | ((unsigned long long)b1 << 32);
        float cnt = (float)(__popc(b0) + __popc(b1));
        g_bits[row] = bits;
        g_rcnt[row] = (cnt > 0.f) ? __fdividef(1.f, cnt) : 0.f;
        g_diag[row] = d * INVT;
    }
}

// ======================= epilogue (templated on diag-tile) =======================
template <bool DG>
__device__ __forceinline__ void epilogue(
    const float (&acc)[2][8][4], int i0, int j0, int it, int jt, int wr, int wc, int lane,
    const unsigned long long* bitsJ, const float* rcJ, const float* dJ) {
    const int q = lane >> 2, sub = lane & 3;
    const int colbase = wc * 64;

    float rS[4], rA[4], rW[4], rP[4], di4[4], rci4[4];
    unsigned long long bi4[4];
    int gi4[4];
#pragma unroll
    for (int g = 0; g < 4; g++) {
        const int gi = i0 + wr * 32 + (g >> 1) * 16 + (g & 1) * 8 + q;
        gi4[g] = gi; bi4[g] = g_bits[gi]; rci4[g] = g_rcnt[gi]; di4[g] = g_diag[gi];
        rS[g] = rA[g] = rW[g] = rP[g] = 0.f;
    }

#pragma unroll
    for (int n = 0; n < 8; n++) {
#pragma unroll
        for (int e = 0; e < 2; e++) {
            const int jl = colbase + n * 8 + sub * 2 + e;
            const int gj = j0 + jl;
            const unsigned long long bj = bitsJ[jl];
            const float rcj = rcJ[jl];
            const float dj = dJ[jl];
            float cS = 0.f, cA = 0.f, cW = 0.f, cP = 0.f;
#pragma unroll
            for (int g = 0; g < 4; g++) {
                const float x = acc[g >> 1][n][(g & 1) * 2 + e];
                float inter = (float)__popcll(bi4[g] & bj);
                float zr = x - di4[g];
                if (DG) {
                    const bool dg = (gi4[g] == gj);
                    inter = dg ? 0.f : inter;
                    zr = dg ? -1e30f : zr;
                }
                const float mu = inter * fminf(rci4[g], rcj);
                const float tv = mu * x;
                const float one = fminf(inter, 1.f);
                rA[g] += tv; rW[g] += mu; rP[g] += one;
                if (zr > -60.f) rS[g] += __expf(zr);     // < 9e-27 below cutoff
                if (!DG) {
                    cA += tv; cW += mu; cP += one;
                    const float zc = x - dj;
                    if (zc > -60.f) cS += __expf(zc);
                }
            }
            if (!DG) {
#pragma unroll
                for (int o = 4; o <= 16; o <<= 1) {
                    cS += __shfl_xor_sync(0xffffffffu, cS, o);
                    cA += __shfl_xor_sync(0xffffffffu, cA, o);
                    cW += __shfl_xor_sync(0xffffffffu, cW, o);
                    cP += __shfl_xor_sync(0xffffffffu, cP, o);
                }
                if (q == 0)
                    g_col4[gj * 128 + it * 4 + wr] = make_float4(cS, cA, cW, cP);
            }
        }
    }

#pragma unroll
    for (int g = 0; g < 4; g++) {
        float S = rS[g], A = rA[g], W = rW[g], P = rP[g];
#pragma unroll
        for (int o = 1; o < 4; o <<= 1) {
            S += __shfl_xor_sync(0xffffffffu, S, o);
            A += __shfl_xor_sync(0xffffffffu, A, o);
            W += __shfl_xor_sync(0xffffffffu, W, o);
            P += __shfl_xor_sync(0xffffffffu, P, o);
        }
        if (sub == 0)
            g_row4[gi4[g] * 64 + jt * 2 + wc] = make_float4(S, A, W, P);
    }
}

// ======================= k2: persistent tile kernel =======================
// smem: A 32KB @0, B 32KB @32768, bitsJ 1KB @65536, rcJ 512B @66560,
//       dJ 512B @67072, ticket 4B @67584.
#define SMEM_BYTES 67648

__global__ __launch_bounds__(NTHR, 2) void supcon_mma() {
    extern __shared__ char smem[];
    const uint32_t sA = smem_u32(smem);
    const uint32_t sB = sA + 32768;
    unsigned long long* bitsJ = (unsigned long long*)(smem + 65536);
    float* rcJ = (float*)(smem + 66560);
    float* dJ = (float*)(smem + 67072);
    int* s_t = (int*)(smem + 67584);

    const int tid = threadIdx.x;
    const int lane = tid & 31, wid = tid >> 5;
    const int wr = wid >> 1, wc = wid & 1;     // warp: 32 rows x 64 cols

    while (true) {
        if (tid == 0) *s_t = atomicAdd(&g_tick, 1);
        __syncthreads();                        // also guards smem reuse across tiles
        const int t = *s_t;
        if (t >= NTILE) return;

        // off-diag tiles (it<jt) first: t<496; diag tiles drain the tail.
        int it, jt;
        if (t < 496) {
            int u = t, r = 31; it = 0;
            while (u >= r) { u -= r; r--; it++; }
            jt = it + 1 + u;
        } else {
            it = jt = t - 496;
        }
        const int i0 = it * TM, j0 = jt * TN;

#pragma unroll
        for (int idx = tid; idx < TM * 16; idx += NTHR) {
            int row = idx >> 4, c16 = idx & 15;
            *(uint4*)(smem + swz(row, c16)) =
                *(const uint4*)(g_fbf + (size_t)(i0 + row) * D + c16 * 8);
        }
#pragma unroll
        for (int idx = tid; idx < TN * 16; idx += NTHR) {
            int row = idx >> 4, c16 = idx & 15;
            *(uint4*)(smem + 32768 + swz(row, c16)) =
                *(const uint4*)(g_fbf + (size_t)(j0 + row) * D + c16 * 8);
        }
#pragma unroll
        for (int x = tid; x < TN; x += NTHR) {
            bitsJ[x] = g_bits[j0 + x];
            rcJ[x] = g_rcnt[j0 + x];
            dJ[x] = g_diag[j0 + x];
        }
        __syncthreads();

        float acc[2][8][4];
#pragma unroll
        for (int m = 0; m < 2; m++)
#pragma unroll
            for (int n = 0; n < 8; n++)
#pragma unroll
                for (int c = 0; c < 4; c++) acc[m][n][c] = 0.f;

        const int lrow = lane & 15, lhalf = lane >> 4;
#pragma unroll 1
        for (int s = 0; s < 8; s++) {   // K = 8 x 16
            uint32_t a[2][4], b[4][4];
#pragma unroll
            for (int m = 0; m < 2; m++)
                ldm_x4(a[m][0], a[m][1], a[m][2], a[m][3],
                       sA + swz(wr * 32 + m * 16 + lrow, 2 * s + lhalf));
#pragma unroll
            for (int g = 0; g < 4; g++)
                ldm_x4(b[g][0], b[g][1], b[g][2], b[g][3],
                       sB + swz(wc * 64 + g * 16 + lrow, 2 * s + lhalf));
#pragma unroll
            for (int m = 0; m < 2; m++)
#pragma unroll
                for (int g = 0; g < 4; g++) {
                    mma16816(acc[m][2 * g + 0], a[m], b[g][0], b[g][2]);
                    mma16816(acc[m][2 * g + 1], a[m], b[g][1], b[g][3]);
                }
        }

        if (it == jt) epilogue<true>(acc, i0, j0, it, jt, wr, wc, lane, bitsJ, rcJ, dJ);
        else          epilogue<false>(acc, i0, j0, it, jt, wr, wc, lane, bitsJ, rcJ, dJ);
    }
}

// ======================= k3: reduce =======================
__global__ void reduce_all(float* __restrict__ out) {
    const int lane = threadIdx.x & 31, w = threadIdx.x >> 5;
    const int row = blockIdx.x * 8 + w;
    const int b = row >> 7;

    float S = 0.f, A = 0.f, W = 0.f, P = 0.f;
    for (int c = 2 * b + lane; c < 64; c += 32) {     // row chunks (jt >= it)
        const float4 v = g_row4[row * 64 + c];
        S += v.x; A += v.y; W += v.z; P += v.w;
    }
    for (int c = lane; c < 4 * b; c += 32) {          // col chunks (it < jt)
        const float4 v = g_col4[row * 128 + c];
        S += v.x; A += v.y; W += v.z; P += v.w;
    }
#pragma unroll
    for (int o = 16; o > 0; o >>= 1) {
        S += __shfl_xor_sync(0xffffffffu, S, o);
        A += __shfl_xor_sync(0xffffffffu, A, o);
        W += __shfl_xor_sync(0xffffffffu, W, o);
        P += __shfl_xor_sync(0xffffffffu, P, o);
    }

    __shared__ float sv[8];
    if (lane == 0) {
        const float di = g_diag[row];
        sv[w] = (A - di * W - W * logf(S + 1e-12f)) / (P + 1e-12f);
    }
    __syncthreads();

    if (w == 0) {
        float t = (lane < 8) ? sv[lane] : 0.f;
#pragma unroll
        for (int o = 4; o > 0; o >>= 1) t += __shfl_xor_sync(0xffffffffu, t, o);

        int is_last = 0;
        if (lane == 0) {
            g_part[blockIdx.x] = t;
            __threadfence();
            is_last = (atomicAdd(&g_sem, 1) == NPART - 1) ? 1 : 0;
        }
        is_last = __shfl_sync(0xffffffffu, is_last, 0);
        if (is_last) {
            __threadfence();
            float s = 0.f;
#pragma unroll
            for (int k = 0; k < NPART / 32; k++)   // fixed order -> deterministic
                s += g_part[lane + k * 32];
#pragma unroll
            for (int o = 16; o > 0; o >>= 1)
                s += __shfl_xor_sync(0xffffffffu, s, o);
            if (lane == 0)
                out[0] = -(s * (1.0f / (float)BATCH)) * 0.5f;   // -mean / 2^alpha
        }
    }
}

extern "C" void kernel_launch(void* const* d_in, const int* in_sizes, int n_in,
                              void* d_out, int out_size) {
    const float* F = (const float*)d_in[0];
    const float* L = (const float*)d_in[1];
    if (n_in >= 2 && in_sizes[0] == BATCH * 50 && in_sizes[1] == BATCH * D) {
        const float* t = F; F = L; L = t;
    }
    cudaFuncSetAttribute(supcon_mma, cudaFuncAttributeMaxDynamicSharedMemorySize, SMEM_BYTES);

    prep_rows<<<BATCH / 8, 256>>>(F, L);
    supcon_mma<<<NPERS, NTHR, SMEM_BYTES>>>();
    reduce_all<<<NPART, 256>>>((float*)d_out);
}